// round 5
// baseline (speedup 1.0000x reference)
#include <cuda_runtime.h>
#include <cuda_bf16.h>
#include <cstdint>

#define Bb 64
#define Vv 64
#define Tt 256
#define Ff 64
#define NEG_SLOPE 0.01f

// Precomputed transposed adjacency: adjT[t][w][v] = sigmoid(A[t][v][w]) off-diag, 1 on diag.
__device__ float g_adjT[(size_t)Tt * Vv * Vv];   // 4 MB

// ---------------------------------------------------------------------------
// Prep: sigmoid exactly once per A element; transpose via smem. ~1.2us.
// ---------------------------------------------------------------------------
__global__ __launch_bounds__(256) void adj_prep(const float* __restrict__ A) {
    const int t = blockIdx.x;
    __shared__ float sm[Vv][Vv + 1];

    const int tid = threadIdx.x;
    const float4* A4 = reinterpret_cast<const float4*>(A) + (size_t)t * 1024;

#pragma unroll
    for (int k = 0; k < 4; k++) {
        int idx4 = tid + k * 256;          // v*16 + wq
        int v = idx4 >> 4, wq = idx4 & 15;
        float4 a = A4[idx4];
        float av[4] = {a.x, a.y, a.z, a.w};
#pragma unroll
        for (int i = 0; i < 4; i++) {
            int w = wq * 4 + i;
            sm[v][w] = (v == w) ? 1.0f
                                : __fdividef(1.0f, 1.0f + __expf(-av[i]));
        }
    }
    __syncthreads();

    float* dst = g_adjT + (size_t)t * 4096;
#pragma unroll
    for (int k = 0; k < 16; k++) {
        int idx = tid + k * 256;           // w*64 + v
        int w = idx >> 6, v = idx & 63;
        dst[idx] = sm[v][w];
    }
}

// ---------------------------------------------------------------------------
// Fused GEMM + expand. 128 threads, 4KB smem, 16 blocks/SM -> grid 2048 is a
// SINGLE wave (no tail). adjT read direct from L1/L2 (warp-coalesced 128B
// rows, no smem staging). GEMM split in two halves interleaved with stores.
// ---------------------------------------------------------------------------
__global__ __launch_bounds__(128, 16) void fused_kernel(const float* __restrict__ X,
                                                        const float* __restrict__ W,
                                                        float* __restrict__ out) {
    const int t  = blockIdx.x;
    const int b0 = blockIdx.y << 3;    // 0,8,...,56

    __shared__ float sX[8][Vv];        // 2 KB
    __shared__ float sH[8][Vv];        // 2 KB

    const int tid = threadIdx.x;

    // Per-thread W quad, leaky pre-selected: leaky(h*w) = h * (h>=0 ? wp : wn)
    float4 w4 = reinterpret_cast<const float4*>(W)[tid & 15];
    float4 wp, wn;
    wp.x = (w4.x >= 0.f) ? w4.x : NEG_SLOPE * w4.x;
    wp.y = (w4.y >= 0.f) ? w4.y : NEG_SLOPE * w4.y;
    wp.z = (w4.z >= 0.f) ? w4.z : NEG_SLOPE * w4.z;
    wp.w = (w4.w >= 0.f) ? w4.w : NEG_SLOPE * w4.w;
    wn.x = (w4.x >= 0.f) ? NEG_SLOPE * w4.x : w4.x;
    wn.y = (w4.y >= 0.f) ? NEG_SLOPE * w4.y : w4.y;
    wn.z = (w4.z >= 0.f) ? NEG_SLOPE * w4.z : w4.z;
    wn.w = (w4.w >= 0.f) ? NEG_SLOPE * w4.w : w4.w;

    // Gather X[b0..b0+7][*][t]
#pragma unroll
    for (int k = 0; k < 4; k++) {
        int idx = tid + k * 128;           // bb*64 + w
        int bb = idx >> 6, w = idx & 63;
        sX[bb][w] = X[((size_t)(b0 + bb) * Vv + w) * Tt + t];
    }
    __syncthreads();

    const int v  = tid & 63;
    const int gp = tid >> 6;               // 0 or 1
    const float* adjt = g_adjT + (size_t)t * 4096 + v;
    const float4* sX4 = reinterpret_cast<const float4*>(sX);
    float4* obase = reinterpret_cast<float4*>(out);

#pragma unroll
    for (int half = 0; half < 2; half++) {
        // GEMM half: rows g0 = gp + 4*half, g1 = g0 + 2  (covers bb 4*half..4*half+3)
        const int g0 = gp + 4 * half;
        const int g1 = g0 + 2;
        float a0 = 0.f, a1 = 0.f;
#pragma unroll
        for (int wq = 0; wq < 16; wq++) {
            float s0 = __ldg(adjt + (4 * wq + 0) * 64);
            float s1 = __ldg(adjt + (4 * wq + 1) * 64);
            float s2 = __ldg(adjt + (4 * wq + 2) * 64);
            float s3 = __ldg(adjt + (4 * wq + 3) * 64);
            float4 x0 = sX4[g0 * 16 + wq];
            float4 x1 = sX4[g1 * 16 + wq];
            a0 = fmaf(s0, x0.x, fmaf(s1, x0.y, fmaf(s2, x0.z, fmaf(s3, x0.w, a0))));
            a1 = fmaf(s0, x1.x, fmaf(s1, x1.y, fmaf(s2, x1.z, fmaf(s3, x1.w, a1))));
        }
        sH[g0][v] = a0;
        sH[g1][v] = a1;
        __syncthreads();

        // Store bb = 4*half .. 4*half+3 : 64 KB of coalesced float4 streaming stores
#pragma unroll
        for (int bi = 0; bi < 4; bi++) {
            int bb = 4 * half + bi;
            float4* o = obase + ((size_t)(b0 + bb) * Tt + t) * 1024;
            const float* hrow = sH[bb];
#pragma unroll
            for (int k = 0; k < 8; k++) {
                int q = tid + k * 128;          // q&15 == tid&15 ; v = q>>4
                float h = hrow[q >> 4];
                bool pos = (h >= 0.f);
                float4 r;
                r.x = h * (pos ? wp.x : wn.x);
                r.y = h * (pos ? wp.y : wn.y);
                r.z = h * (pos ? wp.z : wn.z);
                r.w = h * (pos ? wp.w : wn.w);
                __stcs(o + q, r);
            }
        }
        __syncthreads();   // sH rows about to be overwritten next half
    }
}

extern "C" void kernel_launch(void* const* d_in, const int* in_sizes, int n_in,
                              void* d_out, int out_size) {
    const float* X = (const float*)d_in[0];   // [B, V, T]
    const float* A = (const float*)d_in[1];   // [T, V, V]
    const float* W = (const float*)d_in[2];   // [F, 1]
    float* out = (float*)d_out;               // [B, T, V*F]

    adj_prep<<<Tt, 256>>>(A);
    dim3 grid(Tt, Bb / 8);
    fused_kernel<<<grid, 128>>>(X, W, out);
}

// round 6
// speedup vs baseline: 1.8041x; 1.8041x over previous
#include <cuda_runtime.h>
#include <cuda_bf16.h>
#include <cstdint>

#define Bb 64
#define Vv 64
#define Tt 256
#define Ff 64
#define NEG_SLOPE 0.01f

// Precomputed transposed adjacency: adjT[t][w][v] = sigmoid(A[t][v][w]) off-diag, 1 on diag.
__device__ float g_adjT[(size_t)Tt * Vv * Vv];   // 4 MB

// ---------------------------------------------------------------------------
// Prep: sigmoid exactly once per A element; transpose via smem. ~1.2us.
// ---------------------------------------------------------------------------
__global__ __launch_bounds__(256) void adj_prep(const float* __restrict__ A) {
    const int t = blockIdx.x;
    __shared__ float sm[Vv][Vv + 1];

    const int tid = threadIdx.x;
    const float4* A4 = reinterpret_cast<const float4*>(A) + (size_t)t * 1024;

#pragma unroll
    for (int k = 0; k < 4; k++) {
        int idx4 = tid + k * 256;          // v*16 + wq
        int v = idx4 >> 4, wq = idx4 & 15;
        float4 a = A4[idx4];
        float av[4] = {a.x, a.y, a.z, a.w};
#pragma unroll
        for (int i = 0; i < 4; i++) {
            int w = wq * 4 + i;
            sm[v][w] = (v == w) ? 1.0f
                                : __fdividef(1.0f, 1.0f + __expf(-av[i]));
        }
    }
    __syncthreads();

    float* dst = g_adjT + (size_t)t * 4096;
#pragma unroll
    for (int k = 0; k < 16; k++) {
        int idx = tid + k * 256;           // w*64 + v
        int w = idx >> 6, v = idx & 63;
        dst[idx] = sm[v][w];
    }
}

// ---------------------------------------------------------------------------
// Fused GEMM + expand (round-4 structure, b-group widened 8 -> 16).
// Grid (256, 4) = 1024 blocks, 256 thr, 24 KB smem, 8 blocks/SM -> SINGLE
// wave: prologue paid once, no ragged tail. adjT staged in smem [w][v]
// (warp-contiguous 128B rows). GEMM in 2 chunks interleaved with stores so
// chunk-2 compute hides under chunk-1's 128 KB store stream.
// ---------------------------------------------------------------------------
__global__ __launch_bounds__(256) void fused_kernel(const float* __restrict__ X,
                                                    const float* __restrict__ W,
                                                    float* __restrict__ out) {
    const int t  = blockIdx.x;
    const int b0 = blockIdx.y << 4;    // 0,16,32,48

    __shared__ float sAT[Vv * Vv];     // 16 KB, [w][v]
    __shared__ float sX[16][Vv];       // 4 KB
    __shared__ float sH[16][Vv];       // 4 KB

    const int tid = threadIdx.x;

    // Per-thread W quad, leaky pre-selected: leaky(h*w) = h * (h>=0 ? wp : wn)
    float4 w4 = reinterpret_cast<const float4*>(W)[tid & 15];
    float4 wp, wn;
    wp.x = (w4.x >= 0.f) ? w4.x : NEG_SLOPE * w4.x;
    wp.y = (w4.y >= 0.f) ? w4.y : NEG_SLOPE * w4.y;
    wp.z = (w4.z >= 0.f) ? w4.z : NEG_SLOPE * w4.z;
    wp.w = (w4.w >= 0.f) ? w4.w : NEG_SLOPE * w4.w;
    wn.x = (w4.x >= 0.f) ? NEG_SLOPE * w4.x : w4.x;
    wn.y = (w4.y >= 0.f) ? NEG_SLOPE * w4.y : w4.y;
    wn.z = (w4.z >= 0.f) ? NEG_SLOPE * w4.z : w4.z;
    wn.w = (w4.w >= 0.f) ? NEG_SLOPE * w4.w : w4.w;

    // Stage adjT[t] into smem (16 KB; LDG.128 coalesced, L2-shared across 4 b-groups)
    {
        const float4* src = reinterpret_cast<const float4*>(g_adjT) + (size_t)t * 1024;
        float4* dst = reinterpret_cast<float4*>(sAT);
#pragma unroll
        for (int k = 0; k < 4; k++) dst[tid + k * 256] = src[tid + k * 256];
    }
    // Gather X[b0..b0+15][*][t]
#pragma unroll
    for (int k = 0; k < 4; k++) {
        int idx = tid + k * 256;           // bb*64 + w
        int bb = idx >> 6, w = idx & 63;
        sX[bb][w] = __ldg(&X[((size_t)(b0 + bb) * Vv + w) * Tt + t]);
    }
    __syncthreads();

    const int v = tid & 63;
    const int g = tid >> 6;                // 0..3
    float4* obase = reinterpret_cast<float4*>(out);

#pragma unroll
    for (int chunk = 0; chunk < 2; chunk++) {
        // GEMM chunk: rows r0 = g + 8*chunk, r1 = r0 + 4  (covers bb 8*chunk..8*chunk+7)
        const int r0 = g + 8 * chunk;
        const int r1 = r0 + 4;
        {
            const float4* x0q = reinterpret_cast<const float4*>(&sX[r0][0]);
            const float4* x1q = reinterpret_cast<const float4*>(&sX[r1][0]);
            float a0 = 0.f, a1 = 0.f;
#pragma unroll
            for (int wq = 0; wq < 16; wq++) {
                float s0 = sAT[(4 * wq + 0) * 64 + v];
                float s1 = sAT[(4 * wq + 1) * 64 + v];
                float s2 = sAT[(4 * wq + 2) * 64 + v];
                float s3 = sAT[(4 * wq + 3) * 64 + v];
                float4 x0 = x0q[wq];
                float4 x1 = x1q[wq];
                a0 = fmaf(s0, x0.x, fmaf(s1, x0.y, fmaf(s2, x0.z, fmaf(s3, x0.w, a0))));
                a1 = fmaf(s0, x1.x, fmaf(s1, x1.y, fmaf(s2, x1.z, fmaf(s3, x1.w, a1))));
            }
            sH[r0][v] = a0;
            sH[r1][v] = a1;
        }
        __syncthreads();

        // Store bb = 8*chunk .. 8*chunk+7 : 128 KB of coalesced float4 streaming stores
#pragma unroll
        for (int bi = 0; bi < 8; bi++) {
            int bb = 8 * chunk + bi;
            float4* o = obase + ((size_t)(b0 + bb) * Tt + t) * 1024;
            const float* hrow = sH[bb];
#pragma unroll
            for (int k = 0; k < 4; k++) {
                int q = tid + k * 256;          // q&15 == tid&15 ; v = q>>4
                float h = hrow[q >> 4];
                bool pos = (h >= 0.f);
                float4 r;
                r.x = h * (pos ? wp.x : wn.x);
                r.y = h * (pos ? wp.y : wn.y);
                r.z = h * (pos ? wp.z : wn.z);
                r.w = h * (pos ? wp.w : wn.w);
                __stcs(o + q, r);
            }
        }
    }
}

extern "C" void kernel_launch(void* const* d_in, const int* in_sizes, int n_in,
                              void* d_out, int out_size) {
    const float* X = (const float*)d_in[0];   // [B, V, T]
    const float* A = (const float*)d_in[1];   // [T, V, V]
    const float* W = (const float*)d_in[2];   // [F, 1]
    float* out = (float*)d_out;               // [B, T, V*F]

    adj_prep<<<Tt, 256>>>(A);
    dim3 grid(Tt, Bb / 16);
    fused_kernel<<<grid, 256>>>(X, W, out);
}

// round 7
// speedup vs baseline: 1.8135x; 1.0052x over previous
#include <cuda_runtime.h>
#include <cuda_bf16.h>
#include <cstdint>

#define Bb 64
#define Vv 64
#define Tt 256
#define Ff 64
#define NEG_SLOPE 0.01f

// Precomputed transposed adjacency: adjT[t][w][v] = sigmoid(A[t][v][w]) off-diag, 1 on diag.
__device__ float g_adjT[(size_t)Tt * Vv * Vv];   // 4 MB
// Transposed X: XT[t][b][w] = X[b][w][t]  (makes fused-kernel X loads coalesced)
__device__ float g_XT[(size_t)Tt * Bb * Vv];     // 4 MB

// ---------------------------------------------------------------------------
// Prep 1: sigmoid exactly once per A element; transpose via smem. ~1.2us.
// ---------------------------------------------------------------------------
__global__ __launch_bounds__(256) void adj_prep(const float* __restrict__ A) {
    const int t = blockIdx.x;
    __shared__ float sm[Vv][Vv + 1];

    const int tid = threadIdx.x;
    const float4* A4 = reinterpret_cast<const float4*>(A) + (size_t)t * 1024;

#pragma unroll
    for (int k = 0; k < 4; k++) {
        int idx4 = tid + k * 256;          // v*16 + wq
        int v = idx4 >> 4, wq = idx4 & 15;
        float4 a = A4[idx4];
        float av[4] = {a.x, a.y, a.z, a.w};
#pragma unroll
        for (int i = 0; i < 4; i++) {
            int w = wq * 4 + i;
            sm[v][w] = (v == w) ? 1.0f
                                : __fdividef(1.0f, 1.0f + __expf(-av[i]));
        }
    }
    __syncthreads();

    float* dst = g_adjT + (size_t)t * 4096;
#pragma unroll
    for (int k = 0; k < 16; k++) {
        int idx = tid + k * 256;           // w*64 + v
        int w = idx >> 6, v = idx & 63;
        dst[idx] = sm[v][w];
    }
}

// ---------------------------------------------------------------------------
// Prep 2: X transpose. Block = (tq, b, wq): 32x32 tile, read X coalesced
// along t, write XT coalesced along w. 8 MB total ≈ 1.3us.
// ---------------------------------------------------------------------------
__global__ __launch_bounds__(256) void x_transpose(const float* __restrict__ X) {
    const int t0 = blockIdx.x * 32;    // 0..224
    const int b  = blockIdx.y;         // 0..63
    const int w0 = blockIdx.z * 32;    // 0 or 32

    __shared__ float sm[32][33];

    const int tid = threadIdx.x;
    const int j = tid & 31;            // t offset on read / w offset on write
    const int i0 = tid >> 5;           // 0..7

#pragma unroll
    for (int k = 0; k < 4; k++) {
        int i = i0 + k * 8;            // w offset on read
        sm[i][j] = X[((size_t)b * Vv + (w0 + i)) * Tt + (t0 + j)];
    }
    __syncthreads();
#pragma unroll
    for (int k = 0; k < 4; k++) {
        int i = i0 + k * 8;            // t offset on write
        g_XT[(size_t)(t0 + i) * (Bb * Vv) + (size_t)b * Vv + (w0 + j)] = sm[j][i];
    }
}

// ---------------------------------------------------------------------------
// Fused GEMM + expand — exact round-4 winner shape (2048 blocks, 256 thr,
// 20 KB smem, 8 blocks/SM), with the 1KB-stride X gather replaced by a
// single coalesced 2KB XT load (the gather was ~1M L1tex sector-wavefronts
// chip-wide, contending with the store stream in the same L1tex pipe).
// ---------------------------------------------------------------------------
__global__ __launch_bounds__(256) void fused_kernel(const float* __restrict__ W,
                                                    float* __restrict__ out) {
    const int t  = blockIdx.x;
    const int b0 = blockIdx.y << 3;    // 0,8,...,56

    __shared__ float sAT[Vv * Vv];     // 16 KB, [w][v]
    __shared__ float sX[8][Vv];        // 2 KB
    __shared__ float sH[8][Vv];        // 2 KB

    const int tid = threadIdx.x;

    // Per-thread W quad, leaky pre-selected: leaky(h*w) = h * (h>=0 ? wp : wn)
    float4 w4 = reinterpret_cast<const float4*>(W)[tid & 15];
    float4 wp, wn;
    wp.x = (w4.x >= 0.f) ? w4.x : NEG_SLOPE * w4.x;
    wp.y = (w4.y >= 0.f) ? w4.y : NEG_SLOPE * w4.y;
    wp.z = (w4.z >= 0.f) ? w4.z : NEG_SLOPE * w4.z;
    wp.w = (w4.w >= 0.f) ? w4.w : NEG_SLOPE * w4.w;
    wn.x = (w4.x >= 0.f) ? NEG_SLOPE * w4.x : w4.x;
    wn.y = (w4.y >= 0.f) ? NEG_SLOPE * w4.y : w4.y;
    wn.z = (w4.z >= 0.f) ? NEG_SLOPE * w4.z : w4.z;
    wn.w = (w4.w >= 0.f) ? NEG_SLOPE * w4.w : w4.w;

    // Stage adjT[t] (16 KB, coalesced; L2-resident across the 8 b-groups of t)
    {
        const float4* src = reinterpret_cast<const float4*>(g_adjT) + (size_t)t * 1024;
        float4* dst = reinterpret_cast<float4*>(sAT);
#pragma unroll
        for (int k = 0; k < 4; k++) dst[tid + k * 256] = src[tid + k * 256];
    }
    // Load XT[t][b0..b0+7][0:64] — 512 contiguous floats, fully coalesced.
    if (tid < 128) {
        const float4* src = reinterpret_cast<const float4*>(g_XT + (size_t)t * (Bb * Vv) + (size_t)b0 * Vv);
        reinterpret_cast<float4*>(&sX[0][0])[tid] = src[tid];
    }
    __syncthreads();

    // Mini-GEMM: thread (v = tid&63, g = tid>>6) computes h[g][v], h[g+4][v].
    {
        const int v = tid & 63;
        const int g = tid >> 6;
        const float4* x0q = reinterpret_cast<const float4*>(&sX[g][0]);
        const float4* x1q = reinterpret_cast<const float4*>(&sX[g + 4][0]);
        float a0 = 0.f, a1 = 0.f;
#pragma unroll
        for (int wq = 0; wq < 16; wq++) {
            float4 x0 = x0q[wq];
            float4 x1 = x1q[wq];
            float s0 = sAT[(4 * wq + 0) * 64 + v];
            float s1 = sAT[(4 * wq + 1) * 64 + v];
            float s2 = sAT[(4 * wq + 2) * 64 + v];
            float s3 = sAT[(4 * wq + 3) * 64 + v];
            a0 = fmaf(s0, x0.x, fmaf(s1, x0.y, fmaf(s2, x0.z, fmaf(s3, x0.w, a0))));
            a1 = fmaf(s0, x1.x, fmaf(s1, x1.y, fmaf(s2, x1.z, fmaf(s3, x1.w, a1))));
        }
        sH[g][v] = a0;
        sH[g + 4][v] = a1;
    }
    __syncthreads();

    // Store phase: 8 x 16 KB tiles of leaky(h*W), coalesced float4 streaming stores.
    float4* obase = reinterpret_cast<float4*>(out);
#pragma unroll
    for (int bb = 0; bb < 8; bb++) {
        float4* o = obase + ((size_t)(b0 + bb) * Tt + t) * 1024;
        const float* hrow = sH[bb];
#pragma unroll
        for (int k = 0; k < 4; k++) {
            int q = tid + k * 256;            // q&15 == tid&15, q>>4 = v
            float h = hrow[q >> 4];
            bool pos = (h >= 0.f);
            float4 r;
            r.x = h * (pos ? wp.x : wn.x);
            r.y = h * (pos ? wp.y : wn.y);
            r.z = h * (pos ? wp.z : wn.z);
            r.w = h * (pos ? wp.w : wn.w);
            __stcs(o + q, r);
        }
    }
}

extern "C" void kernel_launch(void* const* d_in, const int* in_sizes, int n_in,
                              void* d_out, int out_size) {
    const float* X = (const float*)d_in[0];   // [B, V, T]
    const float* A = (const float*)d_in[1];   // [T, V, V]
    const float* W = (const float*)d_in[2];   // [F, 1]
    float* out = (float*)d_out;               // [B, T, V*F]

    adj_prep<<<Tt, 256>>>(A);
    dim3 gt(Tt / 32, Bb, Vv / 32);
    x_transpose<<<gt, 256>>>(X);
    dim3 grid(Tt, Bb / 8);
    fused_kernel<<<grid, 256>>>(W, out);
}

// round 8
// speedup vs baseline: 1.9310x; 1.0648x over previous
#include <cuda_runtime.h>
#include <cuda_bf16.h>
#include <cstdint>

#define Bb 64
#define Vv 64
#define Tt 256
#define Ff 64
#define NEG_SLOPE 0.01f

// Precomputed transposed adjacency: adjT[t][w][v] = sigmoid(A[t][v][w]) off-diag, 1 on diag.
__device__ float g_adjT[(size_t)Tt * Vv * Vv];   // 4 MB

__device__ __forceinline__ float fast_sigmoid(float x) {
    // sigmoid(x) = 0.5 + 0.5*tanh(0.5*x): single MUFU.TANH instead of EX2+RCP.
    float th;
    asm("tanh.approx.f32 %0, %1;" : "=f"(th) : "f"(0.5f * x));
    return fmaf(0.5f, th, 0.5f);
}

// ---------------------------------------------------------------------------
// Prep: sigmoid once per A element via MUFU.TANH (half the MUFU ops of
// EX2+RCP — round-7 ncu showed this kernel MUFU-bound at 5.7us, occ 20.6%).
// Grid (t, v-half): 512 blocks for 2x latency coverage. Reads and transposed
// writes both fully 128B-coalesced via a 32x64 smem tile.
// ---------------------------------------------------------------------------
__global__ __launch_bounds__(256) void adj_prep(const float* __restrict__ A) {
    const int t  = blockIdx.x;
    const int v0 = blockIdx.y * 32;    // 0 or 32

    __shared__ float sm[32][Vv + 1];   // [vloc][w]

    const int tid = threadIdx.x;
    const float4* A4 = reinterpret_cast<const float4*>(A) + (size_t)t * 1024 + v0 * 16;

#pragma unroll
    for (int k = 0; k < 2; k++) {
        int idx4 = tid + k * 256;          // vloc*16 + wq
        int vloc = idx4 >> 4, wq = idx4 & 15;
        int v = v0 + vloc;
        float4 a = A4[idx4];
        float av[4] = {a.x, a.y, a.z, a.w};
#pragma unroll
        for (int i = 0; i < 4; i++) {
            int w = wq * 4 + i;
            sm[vloc][w] = (v == w) ? 1.0f : fast_sigmoid(av[i]);
        }
    }
    __syncthreads();

    // Write adjT[t][w][v0..v0+31]: per warp one 128B contiguous segment.
    float* dst = g_adjT + (size_t)t * 4096 + v0;
#pragma unroll
    for (int k = 0; k < 8; k++) {
        int idx = tid + k * 256;           // w*32 + vloc
        int w = idx >> 5, vloc = idx & 31;
        dst[w * 64 + vloc] = sm[vloc][w];
    }
}

// ---------------------------------------------------------------------------
// Fused GEMM + expand — exact round-4 winner (45.6us total): 2048 blocks,
// 256 thr, 20 KB smem, 8 blocks/SM. adjT staged in smem [w][v]; X gathered
// in-kernel (round-7 proved a separate transpose kernel is a net loss).
// ---------------------------------------------------------------------------
__global__ __launch_bounds__(256) void fused_kernel(const float* __restrict__ X,
                                                    const float* __restrict__ W,
                                                    float* __restrict__ out) {
    const int t  = blockIdx.x;
    const int b0 = blockIdx.y << 3;    // 0,8,...,56

    __shared__ float sAT[Vv * Vv];     // 16 KB, [w][v]
    __shared__ float sX[8][Vv];        // 2 KB
    __shared__ float sH[8][Vv];        // 2 KB

    const int tid = threadIdx.x;

    // Per-thread W quad, leaky pre-selected: leaky(h*w) = h * (h>=0 ? wp : wn)
    float4 w4 = reinterpret_cast<const float4*>(W)[tid & 15];
    float4 wp, wn;
    wp.x = (w4.x >= 0.f) ? w4.x : NEG_SLOPE * w4.x;
    wp.y = (w4.y >= 0.f) ? w4.y : NEG_SLOPE * w4.y;
    wp.z = (w4.z >= 0.f) ? w4.z : NEG_SLOPE * w4.z;
    wp.w = (w4.w >= 0.f) ? w4.w : NEG_SLOPE * w4.w;
    wn.x = (w4.x >= 0.f) ? NEG_SLOPE * w4.x : w4.x;
    wn.y = (w4.y >= 0.f) ? NEG_SLOPE * w4.y : w4.y;
    wn.z = (w4.z >= 0.f) ? NEG_SLOPE * w4.z : w4.z;
    wn.w = (w4.w >= 0.f) ? NEG_SLOPE * w4.w : w4.w;

    // Stage adjT[t] (16 KB; LDG.128 coalesced, L2-shared across the 8 b-groups of t)
    {
        const float4* src = reinterpret_cast<const float4*>(g_adjT) + (size_t)t * 1024;
        float4* dst = reinterpret_cast<float4*>(sAT);
#pragma unroll
        for (int k = 0; k < 4; k++) dst[tid + k * 256] = src[tid + k * 256];
    }
    // Gather X[b0..b0+7][*][t]
#pragma unroll
    for (int k = 0; k < 2; k++) {
        int idx = tid + k * 256;           // bb*64 + w
        int bb = idx >> 6, w = idx & 63;
        sX[bb][w] = __ldg(&X[((size_t)(b0 + bb) * Vv + w) * Tt + t]);
    }
    __syncthreads();

    // Mini-GEMM: thread (v = tid&63, g = tid>>6) computes h[g][v], h[g+4][v].
    {
        const int v = tid & 63;
        const int g = tid >> 6;
        const float4* x0q = reinterpret_cast<const float4*>(&sX[g][0]);
        const float4* x1q = reinterpret_cast<const float4*>(&sX[g + 4][0]);
        float a0 = 0.f, a1 = 0.f;
#pragma unroll
        for (int wq = 0; wq < 16; wq++) {
            float4 x0 = x0q[wq];
            float4 x1 = x1q[wq];
            float s0 = sAT[(4 * wq + 0) * 64 + v];
            float s1 = sAT[(4 * wq + 1) * 64 + v];
            float s2 = sAT[(4 * wq + 2) * 64 + v];
            float s3 = sAT[(4 * wq + 3) * 64 + v];
            a0 = fmaf(s0, x0.x, fmaf(s1, x0.y, fmaf(s2, x0.z, fmaf(s3, x0.w, a0))));
            a1 = fmaf(s0, x1.x, fmaf(s1, x1.y, fmaf(s2, x1.z, fmaf(s3, x1.w, a1))));
        }
        sH[g][v] = a0;
        sH[g + 4][v] = a1;
    }
    __syncthreads();

    // Store phase: 8 x 16 KB tiles of leaky(h*W), coalesced float4 streaming stores.
    float4* obase = reinterpret_cast<float4*>(out);
#pragma unroll
    for (int bb = 0; bb < 8; bb++) {
        float4* o = obase + ((size_t)(b0 + bb) * Tt + t) * 1024;
        const float* hrow = sH[bb];
#pragma unroll
        for (int k = 0; k < 4; k++) {
            int q = tid + k * 256;            // q&15 == tid&15, q>>4 = v
            float h = hrow[q >> 4];
            bool pos = (h >= 0.f);
            float4 r;
            r.x = h * (pos ? wp.x : wn.x);
            r.y = h * (pos ? wp.y : wn.y);
            r.z = h * (pos ? wp.z : wn.z);
            r.w = h * (pos ? wp.w : wn.w);
            __stcs(o + q, r);
        }
    }
}

extern "C" void kernel_launch(void* const* d_in, const int* in_sizes, int n_in,
                              void* d_out, int out_size) {
    const float* X = (const float*)d_in[0];   // [B, V, T]
    const float* A = (const float*)d_in[1];   // [T, V, V]
    const float* W = (const float*)d_in[2];   // [F, 1]
    float* out = (float*)d_out;               // [B, T, V*F]

    dim3 gprep(Tt, 2);
    adj_prep<<<gprep, 256>>>(A);
    dim3 grid(Tt, Bb / 8);
    fused_kernel<<<grid, 256>>>(X, W, out);
}